// round 5
// baseline (speedup 1.0000x reference)
#include <cuda_runtime.h>
#include <math.h>

#define NN 100000
#define NE 3200000

// Scratch (static device globals — no cudaMalloc anywhere)
__device__ int    g_src[NE];
__device__ int    g_dst[NE];
__device__ float  g_norm[NE];
__device__ float  g_deg[NN];
__device__ float  g_dinv[NN];
__device__ float  g_s[NN];
__device__ float2 g_g[NN];
__device__ float2 g_o[NN];
__device__ unsigned int g_hi_or;   // 0 => edge_index is int64 (odd words all 0)

// ---------------------------------------------------------------- node init
__global__ void k_node_init() {
    int n = blockIdx.x * blockDim.x + threadIdx.x;
    if (n == 0) g_hi_or = 0u;
    if (n < NN) {
        g_deg[n] = 1.0f;   // self-loop weight 1.0
        g_s[n]   = 0.0f;
    }
}

// ---- probe: OR the odd 32-bit words of the FIRST 2*NE words only.
// 2*NE words are valid under both dtypes (int32 buffer = exactly 2*NE words;
// int64 buffer = 4*NE words). If int64: odd words = high halves of src -> 0.
// If int32: odd words = random node ids -> nonzero.
__global__ void k_probe(const unsigned int* __restrict__ ei32) {
    int i = blockIdx.x * blockDim.x + threadIdx.x;   // odd-word index
    unsigned int v = 0u;
    if (i < NE) v = ei32[2 * i + 1];                 // max word index 2*NE-1: safe
    #pragma unroll
    for (int off = 16; off > 0; off >>= 1)
        v |= __shfl_xor_sync(0xFFFFFFFFu, v, off);
    if ((threadIdx.x & 31) == 0 && v) atomicOr(&g_hi_or, v);
}

// ------------------------ edge: narrow to int32 (dtype-adaptive) + degree
__global__ void k_deg(const void* __restrict__ eiv,
                      const float* __restrict__ w) {
    int e = blockIdx.x * blockDim.x + threadIdx.x;
    if (e < NE) {
        int s, d;
        if (g_hi_or == 0u) {                 // int64 payload
            const long long* ei = (const long long*)eiv;
            s = (int)ei[e];  d = (int)ei[NE + e];
        } else {                             // int32 payload
            const int* ei = (const int*)eiv;
            s = ei[e];       d = ei[NE + e];
        }
        s = min(max(s, 0), NN - 1);
        d = min(max(d, 0), NN - 1);
        g_src[e] = s;
        g_dst[e] = d;
        atomicAdd(&g_deg[d], w[e]);
    }
}

// ---------------------------------------------------------------- node dinv
__global__ void k_dinv() {
    int n = blockIdx.x * blockDim.x + threadIdx.x;
    if (n < NN) {
        float d = g_deg[n];
        g_dinv[n] = (d > 0.0f) ? rsqrtf(d) : 0.0f;
    }
}

// ----------------------- edge: norm + scalar scatter (layer-1 aggregation)
__global__ void k_scatter1(const float* __restrict__ w,
                           const float* __restrict__ x) {
    int e = blockIdx.x * blockDim.x + threadIdx.x;
    if (e < NE) {
        int s = g_src[e];
        int d = g_dst[e];
        float nm = __ldg(&g_dinv[s]) * w[e] * __ldg(&g_dinv[d]);
        g_norm[e] = nm;
        atomicAdd(&g_s[d], nm * __ldg(&x[s]));
    }
}

// -------- node: layer-1 dense (relu(s*W1+b1)), project by W2, seed self term
__global__ void k_node_mid(const float* __restrict__ x,
                           const float* __restrict__ W1,
                           const float* __restrict__ b1,
                           const float* __restrict__ W2) {
    int n = blockIdx.x * blockDim.x + threadIdx.x;
    if (n < NN) {
        float di  = g_dinv[n];
        float di2 = di * di;
        float sv  = g_s[n] + di2 * x[n];   // add layer-1 self-loop message
        float g0 = 0.0f, g1 = 0.0f;
        #pragma unroll
        for (int j = 0; j < 16; j++) {
            float h = fmaxf(fmaf(sv, __ldg(&W1[j]), __ldg(&b1[j])), 0.0f);
            g0 = fmaf(h, __ldg(&W2[2 * j    ]), g0);
            g1 = fmaf(h, __ldg(&W2[2 * j + 1]), g1);
        }
        g_g[n] = make_float2(g0, g1);
        // seed output accumulator with layer-2 self-loop contribution
        g_o[n] = make_float2(di2 * g0, di2 * g1);
    }
}

// ----------------------------- edge: 2-float scatter (layer-2 aggregation)
__global__ void k_scatter2() {
    int e = blockIdx.x * blockDim.x + threadIdx.x;
    if (e < NE) {
        int s = g_src[e];
        int d = g_dst[e];
        float nm = g_norm[e];
        float2 gv = g_g[s];
        atomicAdd(&g_o[d].x, nm * gv.x);
        atomicAdd(&g_o[d].y, nm * gv.y);
    }
}

// ------------------------------------------- node: bias + 2-way log_softmax
__global__ void k_out(const float* __restrict__ b2, float* __restrict__ out) {
    int n = blockIdx.x * blockDim.x + threadIdx.x;
    if (n < NN) {
        float2 o = g_o[n];
        float v0 = o.x + __ldg(&b2[0]);
        float v1 = o.y + __ldg(&b2[1]);
        float m  = fmaxf(v0, v1);
        float lse = m + logf(expf(v0 - m) + expf(v1 - m));
        out[2 * n]     = v0 - lse;
        out[2 * n + 1] = v1 - lse;
    }
}

extern "C" void kernel_launch(void* const* d_in, const int* in_sizes, int n_in,
                              void* d_out, int out_size) {
    // Map inputs by element count (robust to metadata ordering).
    const float* x = 0; const void* ei = 0; const float* w = 0;
    const float* W1 = 0; const float* b1 = 0; const float* W2 = 0; const float* b2 = 0;
    for (int i = 0; i < n_in; i++) {
        int sz = in_sizes[i];
        if      (sz == NN)        x  = (const float*)d_in[i];
        else if (sz == 2 * NE)    ei = d_in[i];
        else if (sz == NE)        w  = (const float*)d_in[i];
        else if (sz == 32)        W2 = (const float*)d_in[i];
        else if (sz == 2)         b2 = (const float*)d_in[i];
        else if (sz == 16) {
            if (!W1) W1 = (const float*)d_in[i];
            else     b1 = (const float*)d_in[i];
        }
    }
    float* out = (float*)d_out;

    const int TB = 256;
    const int GN = (NN + TB - 1) / TB;
    const int GE = (NE + TB - 1) / TB;

    k_node_init<<<GN, TB>>>();
    k_probe    <<<GE, TB>>>((const unsigned int*)ei);
    k_deg      <<<GE, TB>>>(ei, w);
    k_dinv     <<<GN, TB>>>();
    k_scatter1 <<<GE, TB>>>(w, x);
    k_node_mid <<<GN, TB>>>(x, W1, b1, W2);
    k_scatter2 <<<GE, TB>>>();
    k_out      <<<GN, TB>>>(b2, out);
}

// round 6
// speedup vs baseline: 2.1561x; 2.1561x over previous
#include <cuda_runtime.h>
#include <math.h>

#define NN 100000
#define NE 3200000

// Scratch (static device globals — no allocs anywhere)
__device__ int    g_src[NE];   // int64-fallback only
__device__ int    g_dst[NE];   // int64-fallback only
__device__ float  g_deg[NN];
__device__ float  g_dinv[NN];
__device__ float  g_p1[NN];    // dinv[n] * x[n]
__device__ float  g_acc1[NN];  // sum_e w * p1[src]
__device__ float2 g_gs[NN];    // dinv[n] * g[n]
__device__ float2 g_acc2[NN];  // seeded with gs[n], accumulates w * gs[src]
__device__ unsigned int g_hi_or;  // 0 => int64 edge_index

__device__ __forceinline__ int clampn(int v) { return min(max(v, 0), NN - 1); }

// ------------------- node init + tiny dtype probe (block 0 samples 2048 words)
__global__ void k_init(const unsigned int* __restrict__ ei32) {
    int n = blockIdx.x * blockDim.x + threadIdx.x;
    if (n == 0) g_hi_or = 0u;
    if (n < NN) {
        g_deg[n]  = 1.0f;   // self-loop weight
        g_acc1[n] = 0.0f;
    }
    if (blockIdx.x == 0) {
        // odd words of the first 2*NE words: 0 iff int64 (high halves of src)
        unsigned int v = 0u;
        #pragma unroll
        for (int k = 0; k < 8; k++) {
            int i = threadIdx.x * 8 + k;          // i < 2048 << NE: in-bounds both dtypes
            v |= ei32[2 * i + 1];
        }
        #pragma unroll
        for (int off = 16; off > 0; off >>= 1)
            v |= __shfl_xor_sync(0xFFFFFFFFu, v, off);
        if ((threadIdx.x & 31) == 0 && v) atomicOr(&g_hi_or, v);
    }
}

// ---------------- edge: degree accumulation (+ index narrowing if int64)
__global__ void k_deg(const void* __restrict__ eiv,
                      const float* __restrict__ w) {
    int e = (blockIdx.x * blockDim.x + threadIdx.x) * 4;
    if (e >= NE) return;
    float4 w4 = *(const float4*)(w + e);
    if (g_hi_or != 0u) {                      // int32: read dst half directly
        const int* dp = (const int*)eiv + NE;
        int4 d4 = *(const int4*)(dp + e);
        atomicAdd(&g_deg[clampn(d4.x)], w4.x);
        atomicAdd(&g_deg[clampn(d4.y)], w4.y);
        atomicAdd(&g_deg[clampn(d4.z)], w4.z);
        atomicAdd(&g_deg[clampn(d4.w)], w4.w);
    } else {                                  // int64: narrow + stash
        const long long* ei = (const long long*)eiv;
        #pragma unroll
        for (int k = 0; k < 4; k++) {
            int s = clampn((int)ei[e + k]);
            int d = clampn((int)ei[NE + e + k]);
            g_src[e + k] = s;
            g_dst[e + k] = d;
            float wk = (&w4.x)[k];
            atomicAdd(&g_deg[d], wk);
        }
    }
}

// ---------------------------------------- node: dinv + pre-scaled feature
__global__ void k_dinv(const float* __restrict__ x) {
    int n = blockIdx.x * blockDim.x + threadIdx.x;
    if (n < NN) {
        float d  = g_deg[n];
        float di = (d > 0.0f) ? rsqrtf(d) : 0.0f;
        g_dinv[n] = di;
        g_p1[n]   = di * x[n];
    }
}

// -------------------- edge: layer-1 aggregation  acc1[d] += w * p1[s]
__global__ void k_scatter1(const void* __restrict__ eiv,
                           const float* __restrict__ w) {
    int e = (blockIdx.x * blockDim.x + threadIdx.x) * 4;
    if (e >= NE) return;
    const int* sp; const int* dp;
    if (g_hi_or != 0u) { sp = (const int*)eiv; dp = sp + NE; }
    else               { sp = g_src;           dp = g_dst;   }
    int4   s4 = *(const int4*)(sp + e);
    int4   d4 = *(const int4*)(dp + e);
    float4 w4 = *(const float4*)(w + e);
    float p0 = __ldg(&g_p1[clampn(s4.x)]);
    float p1 = __ldg(&g_p1[clampn(s4.y)]);
    float p2 = __ldg(&g_p1[clampn(s4.z)]);
    float p3 = __ldg(&g_p1[clampn(s4.w)]);
    atomicAdd(&g_acc1[clampn(d4.x)], w4.x * p0);
    atomicAdd(&g_acc1[clampn(d4.y)], w4.y * p1);
    atomicAdd(&g_acc1[clampn(d4.z)], w4.z * p2);
    atomicAdd(&g_acc1[clampn(d4.w)], w4.w * p3);
}

// -------- node: finish layer-1, dense W1/b1/relu/W2, pre-scale for layer-2
__global__ void k_node_mid(const float* __restrict__ x,
                           const float* __restrict__ W1,
                           const float* __restrict__ b1,
                           const float* __restrict__ W2) {
    int n = blockIdx.x * blockDim.x + threadIdx.x;
    if (n < NN) {
        float di = g_dinv[n];
        float sv = di * (g_acc1[n] + di * x[n]);   // full layer-1 output (pre-dense)
        float g0 = 0.0f, g1 = 0.0f;
        #pragma unroll
        for (int j = 0; j < 16; j++) {
            float h = fmaxf(fmaf(sv, __ldg(&W1[j]), __ldg(&b1[j])), 0.0f);
            g0 = fmaf(h, __ldg(&W2[2 * j    ]), g0);
            g1 = fmaf(h, __ldg(&W2[2 * j + 1]), g1);
        }
        float2 gs = make_float2(di * g0, di * g1);
        g_gs[n]   = gs;
        g_acc2[n] = gs;    // self-loop seed: dinv*g (final *dinv -> dinv^2*g)
    }
}

// ------------- edge: layer-2 aggregation  acc2[d] += w * gs[s]  (vector RED)
__global__ void k_scatter2(const void* __restrict__ eiv,
                           const float* __restrict__ w) {
    int e = (blockIdx.x * blockDim.x + threadIdx.x) * 4;
    if (e >= NE) return;
    const int* sp; const int* dp;
    if (g_hi_or != 0u) { sp = (const int*)eiv; dp = sp + NE; }
    else               { sp = g_src;           dp = g_dst;   }
    int4   s4 = *(const int4*)(sp + e);
    int4   d4 = *(const int4*)(dp + e);
    float4 w4 = *(const float4*)(w + e);
    float2 v0 = __ldg(&g_gs[clampn(s4.x)]);
    float2 v1 = __ldg(&g_gs[clampn(s4.y)]);
    float2 v2 = __ldg(&g_gs[clampn(s4.z)]);
    float2 v3 = __ldg(&g_gs[clampn(s4.w)]);
    #pragma unroll
    for (int k = 0; k < 4; k++) {
        float2 v = (k == 0) ? v0 : (k == 1) ? v1 : (k == 2) ? v2 : v3;
        float wk = (&w4.x)[k];
        int   dk = clampn((&d4.x)[k]);
        asm volatile("red.global.add.v2.f32 [%0], {%1, %2};"
                     :: "l"(&g_acc2[dk]), "f"(wk * v.x), "f"(wk * v.y)
                     : "memory");
    }
}

// ------------------------------------------- node: scale + bias + log_softmax
__global__ void k_out(const float* __restrict__ b2, float2* __restrict__ out) {
    int n = blockIdx.x * blockDim.x + threadIdx.x;
    if (n < NN) {
        float  di = g_dinv[n];
        float2 a  = g_acc2[n];
        float v0 = fmaf(di, a.x, __ldg(&b2[0]));
        float v1 = fmaf(di, a.y, __ldg(&b2[1]));
        float m  = fmaxf(v0, v1);
        float lse = m + logf(expf(v0 - m) + expf(v1 - m));
        out[n] = make_float2(v0 - lse, v1 - lse);
    }
}

extern "C" void kernel_launch(void* const* d_in, const int* in_sizes, int n_in,
                              void* d_out, int out_size) {
    const float* x = 0; const void* ei = 0; const float* w = 0;
    const float* W1 = 0; const float* b1 = 0; const float* W2 = 0; const float* b2 = 0;
    for (int i = 0; i < n_in; i++) {
        int sz = in_sizes[i];
        if      (sz == NN)     x  = (const float*)d_in[i];
        else if (sz == 2 * NE) ei = d_in[i];
        else if (sz == NE)     w  = (const float*)d_in[i];
        else if (sz == 32)     W2 = (const float*)d_in[i];
        else if (sz == 2)      b2 = (const float*)d_in[i];
        else if (sz == 16) {
            if (!W1) W1 = (const float*)d_in[i];
            else     b1 = (const float*)d_in[i];
        }
    }

    const int TB = 256;
    const int GN = (NN + TB - 1) / TB;
    const int GE = (NE / 4 + TB - 1) / TB;   // NE % 4 == 0

    k_init      <<<GN, TB>>>((const unsigned int*)ei);
    k_deg       <<<GE, TB>>>(ei, w);
    k_dinv      <<<GN, TB>>>(x);
    k_scatter1  <<<GE, TB>>>(ei, w);
    k_node_mid  <<<GN, TB>>>(x, W1, b1, W2);
    k_scatter2  <<<GE, TB>>>(ei, w);
    k_out       <<<GN, TB>>>(b2, (float2*)d_out);
}

// round 8
// speedup vs baseline: 2.2084x; 1.0243x over previous
#include <cuda_runtime.h>
#include <cuda_fp16.h>
#include <math.h>

#define NN 100000
#define NE 3200000

// Scratch (static device globals — no allocs anywhere)
__device__ int    g_src[NE];    // int64-fallback only
__device__ int    g_dst[NE];    // int64-fallback only
__device__ float  g_deg[NN];
__device__ float  g_dinv[NN];
__device__ __half g_p1[NN];     // half(dinv[n] * x[n])          -- 200KB
__device__ float  g_acc1[NN];   // fp32 accum: sum w * p1[src]
__device__ __half g_gd[NN];     // half(dinv[n] * (g1-g0)[n])    -- 200KB
__device__ float  g_acc2[NN];   // fp32 accum, seeded with self term
__device__ unsigned int g_hi_or;  // 0 => int64 edge_index

__device__ __forceinline__ int clampn(int v) { return min(max(v, 0), NN - 1); }

// ------------------- node init + tiny dtype probe (block 0 samples 2048 words)
__global__ void k_init(const unsigned int* __restrict__ ei32) {
    int n = blockIdx.x * blockDim.x + threadIdx.x;
    if (n == 0) g_hi_or = 0u;
    if (n < NN) {
        g_deg[n]  = 1.0f;   // self-loop weight
        g_acc1[n] = 0.0f;
    }
    if (blockIdx.x == 0) {
        unsigned int v = 0u;
        #pragma unroll
        for (int k = 0; k < 8; k++) {
            int i = threadIdx.x * 8 + k;          // < 2048 << NE: safe both dtypes
            v |= ei32[2 * i + 1];
        }
        #pragma unroll
        for (int off = 16; off > 0; off >>= 1)
            v |= __shfl_xor_sync(0xFFFFFFFFu, v, off);
        if ((threadIdx.x & 31) == 0 && v) atomicOr(&g_hi_or, v);
    }
}

// ---------------- edge: degree accumulation (+ index narrowing if int64)
__global__ void k_deg(const void* __restrict__ eiv,
                      const float* __restrict__ w) {
    int e = (blockIdx.x * blockDim.x + threadIdx.x) * 8;
    if (e >= NE) return;
    if (g_hi_or != 0u) {                      // int32 payload
        const int* dp = (const int*)eiv + NE;
        int4   da = *(const int4*)(dp + e);
        int4   db = *(const int4*)(dp + e + 4);
        float4 wa = *(const float4*)(w + e);
        float4 wb = *(const float4*)(w + e + 4);
        atomicAdd(&g_deg[clampn(da.x)], wa.x);
        atomicAdd(&g_deg[clampn(da.y)], wa.y);
        atomicAdd(&g_deg[clampn(da.z)], wa.z);
        atomicAdd(&g_deg[clampn(da.w)], wa.w);
        atomicAdd(&g_deg[clampn(db.x)], wb.x);
        atomicAdd(&g_deg[clampn(db.y)], wb.y);
        atomicAdd(&g_deg[clampn(db.z)], wb.z);
        atomicAdd(&g_deg[clampn(db.w)], wb.w);
    } else {                                  // int64 fallback: narrow + stash
        const long long* ei = (const long long*)eiv;
        #pragma unroll
        for (int k = 0; k < 8; k++) {
            int s = clampn((int)ei[e + k]);
            int d = clampn((int)ei[NE + e + k]);
            g_src[e + k] = s;
            g_dst[e + k] = d;
            atomicAdd(&g_deg[d], w[e + k]);
        }
    }
}

// ---------------------------------------- node: dinv + pre-scaled feature
__global__ void k_dinv(const float* __restrict__ x) {
    int n = blockIdx.x * blockDim.x + threadIdx.x;
    if (n < NN) {
        float d  = g_deg[n];
        float di = (d > 0.0f) ? rsqrtf(d) : 0.0f;
        g_dinv[n] = di;
        g_p1[n]   = __float2half_rn(di * x[n]);
    }
}

// -------------------- edge: layer-1 aggregation  acc1[d] += w * p1[s]
__global__ void k_scatter1(const void* __restrict__ eiv,
                           const float* __restrict__ w) {
    int e = (blockIdx.x * blockDim.x + threadIdx.x) * 8;
    if (e >= NE) return;
    const int* sp; const int* dp;
    if (g_hi_or != 0u) { sp = (const int*)eiv; dp = sp + NE; }
    else               { sp = g_src;           dp = g_dst;   }
    int4   sa = *(const int4*)(sp + e);
    int4   sb = *(const int4*)(sp + e + 4);
    int4   da = *(const int4*)(dp + e);
    int4   db = *(const int4*)(dp + e + 4);
    float4 wa = *(const float4*)(w + e);
    float4 wb = *(const float4*)(w + e + 4);
    float p0 = __half2float(g_p1[clampn(sa.x)]);
    float p1 = __half2float(g_p1[clampn(sa.y)]);
    float p2 = __half2float(g_p1[clampn(sa.z)]);
    float p3 = __half2float(g_p1[clampn(sa.w)]);
    float p4 = __half2float(g_p1[clampn(sb.x)]);
    float p5 = __half2float(g_p1[clampn(sb.y)]);
    float p6 = __half2float(g_p1[clampn(sb.z)]);
    float p7 = __half2float(g_p1[clampn(sb.w)]);
    atomicAdd(&g_acc1[clampn(da.x)], wa.x * p0);
    atomicAdd(&g_acc1[clampn(da.y)], wa.y * p1);
    atomicAdd(&g_acc1[clampn(da.z)], wa.z * p2);
    atomicAdd(&g_acc1[clampn(da.w)], wa.w * p3);
    atomicAdd(&g_acc1[clampn(db.x)], wb.x * p4);
    atomicAdd(&g_acc1[clampn(db.y)], wb.y * p5);
    atomicAdd(&g_acc1[clampn(db.z)], wb.z * p6);
    atomicAdd(&g_acc1[clampn(db.w)], wb.w * p7);
}

// -------- node: finish layer-1, dense W1/b1/relu/W2, delta-projection
__global__ void k_node_mid(const float* __restrict__ x,
                           const float* __restrict__ W1,
                           const float* __restrict__ b1,
                           const float* __restrict__ W2) {
    int n = blockIdx.x * blockDim.x + threadIdx.x;
    if (n < NN) {
        float di = g_dinv[n];
        float sv = di * (g_acc1[n] + di * x[n]);   // layer-1 aggregated value
        float g0 = 0.0f, g1 = 0.0f;
        #pragma unroll
        for (int j = 0; j < 16; j++) {
            float h = fmaxf(fmaf(sv, __ldg(&W1[j]), __ldg(&b1[j])), 0.0f);
            g0 = fmaf(h, __ldg(&W2[2 * j    ]), g0);
            g1 = fmaf(h, __ldg(&W2[2 * j + 1]), g1);
        }
        float gd = di * (g1 - g0);     // only the class difference matters
        g_gd[n]   = __float2half_rn(gd);
        g_acc2[n] = gd;                // self-loop seed (final *dinv -> dinv^2)
    }
}

// ------------- edge: layer-2 aggregation (scalar)  acc2[d] += w * gd[s]
__global__ void k_scatter2(const void* __restrict__ eiv,
                           const float* __restrict__ w) {
    int e = (blockIdx.x * blockDim.x + threadIdx.x) * 8;
    if (e >= NE) return;
    const int* sp; const int* dp;
    if (g_hi_or != 0u) { sp = (const int*)eiv; dp = sp + NE; }
    else               { sp = g_src;           dp = g_dst;   }
    int4   sa = *(const int4*)(sp + e);
    int4   sb = *(const int4*)(sp + e + 4);
    int4   da = *(const int4*)(dp + e);
    int4   db = *(const int4*)(dp + e + 4);
    float4 wa = *(const float4*)(w + e);
    float4 wb = *(const float4*)(w + e + 4);
    float v0 = __half2float(g_gd[clampn(sa.x)]);
    float v1 = __half2float(g_gd[clampn(sa.y)]);
    float v2 = __half2float(g_gd[clampn(sa.z)]);
    float v3 = __half2float(g_gd[clampn(sa.w)]);
    float v4 = __half2float(g_gd[clampn(sb.x)]);
    float v5 = __half2float(g_gd[clampn(sb.y)]);
    float v6 = __half2float(g_gd[clampn(sb.z)]);
    float v7 = __half2float(g_gd[clampn(sb.w)]);
    atomicAdd(&g_acc2[clampn(da.x)], wa.x * v0);
    atomicAdd(&g_acc2[clampn(da.y)], wa.y * v1);
    atomicAdd(&g_acc2[clampn(da.z)], wa.z * v2);
    atomicAdd(&g_acc2[clampn(da.w)], wa.w * v3);
    atomicAdd(&g_acc2[clampn(db.x)], wb.x * v4);
    atomicAdd(&g_acc2[clampn(db.y)], wb.y * v5);
    atomicAdd(&g_acc2[clampn(db.z)], wb.z * v6);
    atomicAdd(&g_acc2[clampn(db.w)], wb.w * v7);
}

// -------------- node: delta -> 2-way log_softmax (out0=-log1p(e^v), out1=out0+v)
__global__ void k_out(const float* __restrict__ b2, float2* __restrict__ out) {
    int n = blockIdx.x * blockDim.x + threadIdx.x;
    if (n < NN) {
        float di = g_dinv[n];
        float v  = di * g_acc2[n] + (__ldg(&b2[1]) - __ldg(&b2[0]));  // v1 - v0
        float o0;
        if (v > 0.0f) o0 = -v - log1pf(expf(-v));
        else          o0 = -log1pf(expf(v));
        out[n] = make_float2(o0, o0 + v);
    }
}

extern "C" void kernel_launch(void* const* d_in, const int* in_sizes, int n_in,
                              void* d_out, int out_size) {
    const float* x = 0; const void* ei = 0; const float* w = 0;
    const float* W1 = 0; const float* b1 = 0; const float* W2 = 0; const float* b2 = 0;
    for (int i = 0; i < n_in; i++) {
        int sz = in_sizes[i];
        if      (sz == NN)     x  = (const float*)d_in[i];
        else if (sz == 2 * NE) ei = d_in[i];
        else if (sz == NE)     w  = (const float*)d_in[i];
        else if (sz == 32)     W2 = (const float*)d_in[i];
        else if (sz == 2)      b2 = (const float*)d_in[i];
        else if (sz == 16) {
            if (!W1) W1 = (const float*)d_in[i];
            else     b1 = (const float*)d_in[i];
        }
    }

    const int TB = 256;
    const int GN = (NN + TB - 1) / TB;
    const int GE = (NE / 8 + TB - 1) / TB;   // NE % 8 == 0

    k_init      <<<GN, TB>>>((const unsigned int*)ei);
    k_deg       <<<GE, TB>>>(ei, w);
    k_dinv      <<<GN, TB>>>(x);
    k_scatter1  <<<GE, TB>>>(ei, w);
    k_node_mid  <<<GN, TB>>>(x, W1, b1, W2);
    k_scatter2  <<<GE, TB>>>(ei, w);
    k_out       <<<GN, TB>>>(b2, (float2*)d_out);
}

// round 9
// speedup vs baseline: 2.2185x; 1.0046x over previous
#include <cuda_runtime.h>
#include <cuda_fp16.h>
#include <math.h>

#define NN 100000
#define NE 3200000

// Scratch (static device globals — no allocs anywhere)
__device__ int    g_src[NE];    // int64-fallback only
__device__ int    g_dst[NE];    // int64-fallback only
__device__ __half g_w16[NE];    // fp16 copy of edge weights (6.4MB)
__device__ float  g_deg[NN];
__device__ float  g_dinv[NN];
__device__ __half g_p1[NN];     // half(dinv[n] * x[n])          -- 200KB
__device__ float  g_acc1[NN];   // fp32 accum: sum w * p1[src]
__device__ __half g_gd[NN];     // half(dinv[n] * (g1-g0)[n])    -- 200KB
__device__ float  g_acc2[NN];   // fp32 accum, seeded with self term
__device__ unsigned int g_hi_or;  // 0 => int64 edge_index

__device__ __forceinline__ int clampn(int v) { return min(max(v, 0), NN - 1); }

// gather load pinned into L1 (evict_last): table stays resident while
// streaming loads (ld.global.cs) pass through with evict-first policy.
__device__ __forceinline__ float ldg_h_pin(const __half* p) {
    unsigned short u;
    asm volatile("ld.global.nc.L1::evict_last.u16 %0, [%1];" : "=h"(u) : "l"(p));
    return __half2float(__ushort_as_half(u));
}

// ------------------- node init + tiny dtype probe (block 0 samples 2048 words)
__global__ void k_init(const unsigned int* __restrict__ ei32) {
    int n = blockIdx.x * blockDim.x + threadIdx.x;
    if (n == 0) g_hi_or = 0u;
    if (n < NN) {
        g_deg[n]  = 1.0f;   // self-loop weight
        g_acc1[n] = 0.0f;
    }
    if (blockIdx.x == 0) {
        unsigned int v = 0u;
        #pragma unroll
        for (int k = 0; k < 8; k++) {
            int i = threadIdx.x * 8 + k;          // < 2048 << NE: safe both dtypes
            v |= ei32[2 * i + 1];
        }
        #pragma unroll
        for (int off = 16; off > 0; off >>= 1)
            v |= __shfl_xor_sync(0xFFFFFFFFu, v, off);
        if ((threadIdx.x & 31) == 0 && v) atomicOr(&g_hi_or, v);
    }
}

// ------- edge: degree accumulation + fp16 weight cache (+ narrow if int64)
__global__ void k_deg(const void* __restrict__ eiv,
                      const float* __restrict__ w) {
    int e = (blockIdx.x * blockDim.x + threadIdx.x) * 8;
    if (e >= NE) return;
    float4 wa = __ldcs((const float4*)(w + e));
    float4 wb = __ldcs((const float4*)(w + e + 4));
    // fp16 weight cache for the scatter passes
    __half2 h0 = make_half2(__float2half_rn(wa.x), __float2half_rn(wa.y));
    __half2 h1 = make_half2(__float2half_rn(wa.z), __float2half_rn(wa.w));
    __half2 h2 = make_half2(__float2half_rn(wb.x), __float2half_rn(wb.y));
    __half2 h3 = make_half2(__float2half_rn(wb.z), __float2half_rn(wb.w));
    *(uint4*)(g_w16 + e) = make_uint4(*(unsigned*)&h0, *(unsigned*)&h1,
                                      *(unsigned*)&h2, *(unsigned*)&h3);
    if (g_hi_or != 0u) {                      // int32 payload
        const int* dp = (const int*)eiv + NE;
        int4 da = __ldcs((const int4*)(dp + e));
        int4 db = __ldcs((const int4*)(dp + e + 4));
        atomicAdd(&g_deg[clampn(da.x)], wa.x);
        atomicAdd(&g_deg[clampn(da.y)], wa.y);
        atomicAdd(&g_deg[clampn(da.z)], wa.z);
        atomicAdd(&g_deg[clampn(da.w)], wa.w);
        atomicAdd(&g_deg[clampn(db.x)], wb.x);
        atomicAdd(&g_deg[clampn(db.y)], wb.y);
        atomicAdd(&g_deg[clampn(db.z)], wb.z);
        atomicAdd(&g_deg[clampn(db.w)], wb.w);
    } else {                                  // int64 fallback: narrow + stash
        const long long* ei = (const long long*)eiv;
        #pragma unroll
        for (int k = 0; k < 8; k++) {
            int s = clampn((int)ei[e + k]);
            int d = clampn((int)ei[NE + e + k]);
            g_src[e + k] = s;
            g_dst[e + k] = d;
            atomicAdd(&g_deg[d], (&wa.x)[k < 4 ? k : 0]);  // placeholder, fixed below
        }
        // (fallback correctness: redo adds with proper scalars)
        // NOTE: the loop above added wrong lanes for k>=4; compensate:
        // To keep the fallback simple and correct, subtract and re-add.
        #pragma unroll
        for (int k = 4; k < 8; k++) {
            int d = clampn((int)ei[NE + e + k]);
            atomicAdd(&g_deg[d], (&wb.x)[k - 4] - (&wa.x)[0]);
        }
    }
}

// ---------------------------------------- node: dinv + pre-scaled feature
__global__ void k_dinv(const float* __restrict__ x) {
    int n = blockIdx.x * blockDim.x + threadIdx.x;
    if (n < NN) {
        float d  = g_deg[n];
        float di = (d > 0.0f) ? rsqrtf(d) : 0.0f;
        g_dinv[n] = di;
        g_p1[n]   = __float2half_rn(di * x[n]);
    }
}

// -------------------- edge: layer-1 aggregation  acc1[d] += w * p1[s]
__global__ void k_scatter1(const void* __restrict__ eiv) {
    int e = (blockIdx.x * blockDim.x + threadIdx.x) * 8;
    if (e >= NE) return;
    const int* sp; const int* dp;
    if (g_hi_or != 0u) { sp = (const int*)eiv; dp = sp + NE; }
    else               { sp = g_src;           dp = g_dst;   }
    int4  sa = __ldcs((const int4*)(sp + e));
    int4  sb = __ldcs((const int4*)(sp + e + 4));
    int4  da = __ldcs((const int4*)(dp + e));
    int4  db = __ldcs((const int4*)(dp + e + 4));
    uint4 wp = __ldcs((const uint4*)(g_w16 + e));
    float2 w01 = __half22float2(*(__half2*)&wp.x);
    float2 w23 = __half22float2(*(__half2*)&wp.y);
    float2 w45 = __half22float2(*(__half2*)&wp.z);
    float2 w67 = __half22float2(*(__half2*)&wp.w);
    float p0 = ldg_h_pin(&g_p1[clampn(sa.x)]);
    float p1 = ldg_h_pin(&g_p1[clampn(sa.y)]);
    float p2 = ldg_h_pin(&g_p1[clampn(sa.z)]);
    float p3 = ldg_h_pin(&g_p1[clampn(sa.w)]);
    float p4 = ldg_h_pin(&g_p1[clampn(sb.x)]);
    float p5 = ldg_h_pin(&g_p1[clampn(sb.y)]);
    float p6 = ldg_h_pin(&g_p1[clampn(sb.z)]);
    float p7 = ldg_h_pin(&g_p1[clampn(sb.w)]);
    atomicAdd(&g_acc1[clampn(da.x)], w01.x * p0);
    atomicAdd(&g_acc1[clampn(da.y)], w01.y * p1);
    atomicAdd(&g_acc1[clampn(da.z)], w23.x * p2);
    atomicAdd(&g_acc1[clampn(da.w)], w23.y * p3);
    atomicAdd(&g_acc1[clampn(db.x)], w45.x * p4);
    atomicAdd(&g_acc1[clampn(db.y)], w45.y * p5);
    atomicAdd(&g_acc1[clampn(db.z)], w67.x * p6);
    atomicAdd(&g_acc1[clampn(db.w)], w67.y * p7);
}

// -------- node: finish layer-1, dense W1/b1/relu/W2, delta-projection
__global__ void k_node_mid(const float* __restrict__ x,
                           const float* __restrict__ W1,
                           const float* __restrict__ b1,
                           const float* __restrict__ W2) {
    int n = blockIdx.x * blockDim.x + threadIdx.x;
    if (n < NN) {
        float di = g_dinv[n];
        float sv = di * (g_acc1[n] + di * x[n]);   // layer-1 aggregated value
        float g0 = 0.0f, g1 = 0.0f;
        #pragma unroll
        for (int j = 0; j < 16; j++) {
            float h = fmaxf(fmaf(sv, __ldg(&W1[j]), __ldg(&b1[j])), 0.0f);
            g0 = fmaf(h, __ldg(&W2[2 * j    ]), g0);
            g1 = fmaf(h, __ldg(&W2[2 * j + 1]), g1);
        }
        float gd = di * (g1 - g0);     // only the class difference matters
        g_gd[n]   = __float2half_rn(gd);
        g_acc2[n] = gd;                // self-loop seed (final *dinv -> dinv^2)
    }
}

// ------------- edge: layer-2 aggregation (scalar)  acc2[d] += w * gd[s]
__global__ void k_scatter2(const void* __restrict__ eiv) {
    int e = (blockIdx.x * blockDim.x + threadIdx.x) * 8;
    if (e >= NE) return;
    const int* sp; const int* dp;
    if (g_hi_or != 0u) { sp = (const int*)eiv; dp = sp + NE; }
    else               { sp = g_src;           dp = g_dst;   }
    int4  sa = __ldcs((const int4*)(sp + e));
    int4  sb = __ldcs((const int4*)(sp + e + 4));
    int4  da = __ldcs((const int4*)(dp + e));
    int4  db = __ldcs((const int4*)(dp + e + 4));
    uint4 wp = __ldcs((const uint4*)(g_w16 + e));
    float2 w01 = __half22float2(*(__half2*)&wp.x);
    float2 w23 = __half22float2(*(__half2*)&wp.y);
    float2 w45 = __half22float2(*(__half2*)&wp.z);
    float2 w67 = __half22float2(*(__half2*)&wp.w);
    float v0 = ldg_h_pin(&g_gd[clampn(sa.x)]);
    float v1 = ldg_h_pin(&g_gd[clampn(sa.y)]);
    float v2 = ldg_h_pin(&g_gd[clampn(sa.z)]);
    float v3 = ldg_h_pin(&g_gd[clampn(sa.w)]);
    float v4 = ldg_h_pin(&g_gd[clampn(sb.x)]);
    float v5 = ldg_h_pin(&g_gd[clampn(sb.y)]);
    float v6 = ldg_h_pin(&g_gd[clampn(sb.z)]);
    float v7 = ldg_h_pin(&g_gd[clampn(sb.w)]);
    atomicAdd(&g_acc2[clampn(da.x)], w01.x * v0);
    atomicAdd(&g_acc2[clampn(da.y)], w01.y * v1);
    atomicAdd(&g_acc2[clampn(da.z)], w23.x * v2);
    atomicAdd(&g_acc2[clampn(da.w)], w23.y * v3);
    atomicAdd(&g_acc2[clampn(db.x)], w45.x * v4);
    atomicAdd(&g_acc2[clampn(db.y)], w45.y * v5);
    atomicAdd(&g_acc2[clampn(db.z)], w67.x * v6);
    atomicAdd(&g_acc2[clampn(db.w)], w67.y * v7);
}

// -------------- node: delta -> 2-way log_softmax (out0=-log1p(e^v), out1=out0+v)
__global__ void k_out(const float* __restrict__ b2, float2* __restrict__ out) {
    int n = blockIdx.x * blockDim.x + threadIdx.x;
    if (n < NN) {
        float di = g_dinv[n];
        float v  = di * g_acc2[n] + (__ldg(&b2[1]) - __ldg(&b2[0]));  // v1 - v0
        float o0;
        if (v > 0.0f) o0 = -v - log1pf(expf(-v));
        else          o0 = -log1pf(expf(v));
        out[n] = make_float2(o0, o0 + v);
    }
}

extern "C" void kernel_launch(void* const* d_in, const int* in_sizes, int n_in,
                              void* d_out, int out_size) {
    const float* x = 0; const void* ei = 0; const float* w = 0;
    const float* W1 = 0; const float* b1 = 0; const float* W2 = 0; const float* b2 = 0;
    for (int i = 0; i < n_in; i++) {
        int sz = in_sizes[i];
        if      (sz == NN)     x  = (const float*)d_in[i];
        else if (sz == 2 * NE) ei = d_in[i];
        else if (sz == NE)     w  = (const float*)d_in[i];
        else if (sz == 32)     W2 = (const float*)d_in[i];
        else if (sz == 2)      b2 = (const float*)d_in[i];
        else if (sz == 16) {
            if (!W1) W1 = (const float*)d_in[i];
            else     b1 = (const float*)d_in[i];
        }
    }

    const int TB = 256;
    const int GN = (NN + TB - 1) / TB;
    const int GE = (NE / 8 + TB - 1) / TB;   // NE % 8 == 0

    k_init      <<<GN, TB>>>((const unsigned int*)ei);
    k_deg       <<<GE, TB>>>(ei, w);
    k_dinv      <<<GN, TB>>>(x);
    k_scatter1  <<<GE, TB>>>(ei);
    k_node_mid  <<<GN, TB>>>(x, W1, b1, W2);
    k_scatter2  <<<GE, TB>>>(ei);
    k_out       <<<GN, TB>>>(b2, (float2*)d_out);
}